// round 1
// baseline (speedup 1.0000x reference)
#include <cuda_runtime.h>

#define BATCH 16
#define FDIM  512
#define TDIM  4000
#define PDIM  100
#define WIN   40
#define KD    256
#define ROWS  (BATCH*FDIM)     // 8192
#define NF4   (TDIM/4)         // 1000 float4 per row

#define FT 64                  // f-tile rows per block
#define GT 64                  // g-tile cols per iteration
#define PADW 68                // padded row width for transposed smem tiles

// ---------------- scratch (__device__ globals; no allocation) ----------------
__device__ float g_pooled[ROWS*PDIM];   // P  [B*F, 100]
__device__ float g_xmean [ROWS];        // mean over T
__device__ float g_Amat  [PDIM*PDIM];   // (Wk^T Wq)/16
__device__ float g_wqb   [PDIM];        // (Wq^T bk)/16
__device__ float g_fw    [ROWS];
__device__ float g_fwn   [ROWS];

// ---------------- kernel A: adaptive avg pool + row mean ----------------
__global__ void pool_kernel(const float* __restrict__ x) {
    int row = blockIdx.x;
    const float4* xr = (const float4*)(x + (size_t)row*TDIM);
    __shared__ float s_part[NF4];
    __shared__ float s_win[PDIM];
    int tid = threadIdx.x;                 // 256 threads
    for (int i = tid; i < NF4; i += 256) {
        float4 v = xr[i];
        s_part[i] = (v.x + v.y) + (v.z + v.w);
    }
    __syncthreads();
    if (tid < PDIM) {
        float s = 0.f;
        #pragma unroll
        for (int k = 0; k < 10; k++) s += s_part[tid*10 + k];
        s_win[tid] = s;
        g_pooled[row*PDIM + tid] = s * (1.0f/WIN);
    }
    __syncthreads();
    if (tid < 32) {
        float t = 0.f;
        for (int w = tid; w < PDIM; w += 32) t += s_win[w];
        #pragma unroll
        for (int off = 16; off; off >>= 1) t += __shfl_down_sync(0xffffffffu, t, off);
        if (tid == 0) g_xmean[row] = t * (1.0f/TDIM);
    }
}

// ---------------- kernel B: A = (Wk^T Wq)/16, wqb = (Wq^T bk)/16 ----------------
__global__ void prep_kernel(const float* __restrict__ Wk,
                            const float* __restrict__ Wq,
                            const float* __restrict__ bk) {
    int i = blockIdx.x;        // 0..99 -> A row i ; 100 -> wqb
    int j = threadIdx.x;       // 128 threads, use j<100
    if (j >= PDIM) return;
    float acc = 0.f;
    if (i < PDIM) {
        for (int d = 0; d < KD; d++)
            acc += Wk[d*PDIM + i] * Wq[d*PDIM + j];   // coalesced over j, bcast Wk
        g_Amat[i*PDIM + j] = acc * (1.0f/16.0f);
    } else {
        for (int d = 0; d < KD; d++)
            acc += Wq[d*PDIM + j] * bk[d];
        g_wqb[j] = acc * (1.0f/16.0f);
    }
}

// ---------------- kernel C: scores = P A P^T + v ; online softmax -> fw ----------------
// grid (FDIM/FT, BATCH), 256 threads (16x16), 4x4 micro-tile
__global__ void att_kernel() {
    extern __shared__ float sm[];
    float* sA    = sm;                    // 10000
    float* sPT   = sA   + PDIM*PDIM;      // 100*68 = 6800 (transposed P tile [i][g])
    float* sDT   = sPT  + PDIM*PADW;      // 6800 (transposed D=P_f A, [i2][r])
    float* s_v   = sDT  + PDIM*PADW;      // 64
    float* s_xm  = s_v  + GT;             // 64
    float* s_wqb = s_xm + GT;             // 100

    int b  = blockIdx.y;
    int f0 = blockIdx.x * FT;
    int tid = threadIdx.x;
    int tx = tid & 15, ty = tid >> 4;

    const float* Pb = g_pooled + (size_t)b*FDIM*PDIM;

    for (int idx = tid; idx < PDIM*PDIM; idx += 256) sA[idx] = g_Amat[idx];
    if (tid < PDIM) s_wqb[tid] = g_wqb[tid];

    // load f-tile of P, transposed
    for (int idx = tid; idx < FT*PDIM; idx += 256) {
        int r = idx / PDIM, i = idx % PDIM;
        sPT[i*PADW + r] = Pb[(f0 + r)*PDIM + i];
    }
    __syncthreads();

    // D^T[i2][r] = sum_i A[i][i2] * P_f^T[i][r]
    for (int i2 = ty; i2 < PDIM; i2 += 16) {
        float4 acc = make_float4(0.f, 0.f, 0.f, 0.f);
        for (int i = 0; i < PDIM; i++) {
            float a = sA[i*PDIM + i2];
            float4 p = *(const float4*)(sPT + i*PADW + 4*tx);
            acc.x += a*p.x; acc.y += a*p.y; acc.z += a*p.z; acc.w += a*p.w;
        }
        *(float4*)(sDT + i2*PADW + 4*tx) = acc;
    }

    float num[4] = {0.f,0.f,0.f,0.f};
    float den[4] = {0.f,0.f,0.f,0.f};

    for (int g0 = 0; g0 < FDIM; g0 += GT) {
        __syncthreads();   // previous tile fully consumed before overwrite
        for (int idx = tid; idx < GT*PDIM; idx += 256) {
            int g = idx / PDIM, i = idx % PDIM;
            sPT[i*PADW + g] = Pb[(g0 + g)*PDIM + i];
        }
        if (tid < GT) s_xm[tid] = g_xmean[b*FDIM + g0 + tid];
        __syncthreads();
        if (tid < GT) {
            float v = 0.f;
            for (int i = 0; i < PDIM; i++) v += sPT[i*PADW + tid] * s_wqb[i];
            s_v[tid] = v;
        }
        __syncthreads();

        float acc[4][4] = {};
        #pragma unroll 2
        for (int i2 = 0; i2 < PDIM; i2++) {
            float4 d = *(const float4*)(sDT + i2*PADW + 4*ty);
            float4 p = *(const float4*)(sPT + i2*PADW + 4*tx);
            acc[0][0] += d.x*p.x; acc[0][1] += d.x*p.y; acc[0][2] += d.x*p.z; acc[0][3] += d.x*p.w;
            acc[1][0] += d.y*p.x; acc[1][1] += d.y*p.y; acc[1][2] += d.y*p.z; acc[1][3] += d.y*p.w;
            acc[2][0] += d.z*p.x; acc[2][1] += d.z*p.y; acc[2][2] += d.z*p.z; acc[2][3] += d.z*p.w;
            acc[3][0] += d.w*p.x; acc[3][1] += d.w*p.y; acc[3][2] += d.w*p.z; acc[3][3] += d.w*p.w;
        }
        #pragma unroll
        for (int rk = 0; rk < 4; rk++) {
            #pragma unroll
            for (int ck = 0; ck < 4; ck++) {
                float e = __expf(acc[rk][ck] + s_v[4*tx + ck]);  // scores tiny -> no max needed
                den[rk] += e;
                num[rk] += e * s_xm[4*tx + ck];
            }
        }
    }

    // reduce across the 16 tx lanes (16-lane segments of each warp)
    #pragma unroll
    for (int rk = 0; rk < 4; rk++) {
        float n = num[rk], d = den[rk];
        #pragma unroll
        for (int off = 8; off; off >>= 1) {
            n += __shfl_down_sync(0xffffffffu, n, off, 16);
            d += __shfl_down_sync(0xffffffffu, d, off, 16);
        }
        if (tx == 0) g_fw[b*FDIM + f0 + 4*ty + rk] = n / d;
    }
}

// ---------------- kernel D: per-batch min/max normalize ----------------
__global__ void norm_kernel() {
    int b = blockIdx.x;
    int f = threadIdx.x;        // 512
    float v = g_fw[b*FDIM + f];
    __shared__ float smin[16], smax[16];
    float mn = v, mx = v;
    #pragma unroll
    for (int off = 16; off; off >>= 1) {
        mn = fminf(mn, __shfl_down_sync(0xffffffffu, mn, off));
        mx = fmaxf(mx, __shfl_down_sync(0xffffffffu, mx, off));
    }
    if ((f & 31) == 0) { smin[f >> 5] = mn; smax[f >> 5] = mx; }
    __syncthreads();
    if (f < 16) {
        mn = smin[f]; mx = smax[f];
        #pragma unroll
        for (int off = 8; off; off >>= 1) {
            mn = fminf(mn, __shfl_down_sync(0x0000ffffu, mn, off, 16));
            mx = fmaxf(mx, __shfl_down_sync(0x0000ffffu, mx, off, 16));
        }
        if (f == 0) { smin[0] = mn; smax[0] = mx; }
    }
    __syncthreads();
    float mi = smin[0], ma = smax[0];
    g_fwn[b*FDIM + f] = (v - mi) / (ma - mi) + 1e-6f;
}

// ---------------- kernel E: out = x * fw_n ----------------
__global__ void scale_kernel(const float* __restrict__ x, float* __restrict__ out) {
    int row = blockIdx.x;
    float s = g_fwn[row];
    const float4* xr = (const float4*)(x   + (size_t)row*TDIM);
    float4*       orow = (float4*)(out + (size_t)row*TDIM);
    for (int i = threadIdx.x; i < NF4; i += 256) {
        float4 v = xr[i];
        v.x *= s; v.y *= s; v.z *= s; v.w *= s;
        orow[i] = v;
    }
}

// ---------------- launch ----------------
extern "C" void kernel_launch(void* const* d_in, const int* in_sizes, int n_in,
                              void* d_out, int out_size) {
    const float* x  = (const float*)d_in[0];
    const float* Wk = (const float*)d_in[1];
    const float* bk = (const float*)d_in[2];
    const float* Wq = (const float*)d_in[3];
    const float* bq = (const float*)d_in[4];
    (void)bq; (void)in_sizes; (void)n_in; (void)out_size;
    float* out = (float*)d_out;

    const int smem_att = (PDIM*PDIM + 2*PDIM*PADW + 2*GT + PDIM) * sizeof(float); // ~95.3KB
    cudaFuncSetAttribute(att_kernel, cudaFuncAttributeMaxDynamicSharedMemorySize, smem_att);

    pool_kernel<<<ROWS, 256>>>(x);
    prep_kernel<<<PDIM + 1, 128>>>(Wk, Wq, bk);
    dim3 agrid(FDIM/FT, BATCH);
    att_kernel<<<agrid, 256, smem_att>>>();
    norm_kernel<<<BATCH, FDIM>>>();
    scale_kernel<<<ROWS, 256>>>(x, out);
}

// round 2
// speedup vs baseline: 1.0080x; 1.0080x over previous
#include <cuda_runtime.h>

#define BATCH 16
#define FDIM  512
#define TDIM  4000
#define PDIM  100
#define WIN   40
#define KD    256
#define ROWS  (BATCH*FDIM)     // 8192
#define NF4   (TDIM/4)         // 1000 float4 per row

#define FT 64                  // f-tile rows per att block
#define GT 64                  // g-tile cols per iteration
#define DVPAD 68               // padded stride in dv transpose tile (16B-aligned)

// ---------------- scratch (__device__ globals; no allocation) ----------------
__device__ float g_pooled[ROWS*PDIM];        // P [B*F,100]
__device__ float g_xmean [ROWS];
__device__ float g_Amat  [PDIM*PDIM];        // (Wk^T Wq)/16
__device__ float g_wqb   [PDIM];             // (Wq^T bk)/16
__device__ float g_Dt    [BATCH*PDIM*FDIM];  // D^T per batch: [b][i2][f]
__device__ float g_Pt    [BATCH*PDIM*FDIM];  // P^T per batch: [b][i][g]
__device__ float g_v     [ROWS];             // v = P . wqb
__device__ float g_fw    [ROWS];

// ---------------- packed f32x2 helpers ----------------
__device__ __forceinline__ unsigned long long pk2(float lo, float hi) {
    unsigned long long r;
    asm("mov.b64 %0,{%1,%2};" : "=l"(r) : "f"(lo), "f"(hi));
    return r;
}
__device__ __forceinline__ unsigned long long fma2(unsigned long long a,
                                                   unsigned long long b,
                                                   unsigned long long c) {
    unsigned long long d;
    asm("fma.rn.f32x2 %0,%1,%2,%3;" : "=l"(d) : "l"(a), "l"(b), "l"(c));
    return d;
}
__device__ __forceinline__ void unpk2(unsigned long long v, float& lo, float& hi) {
    asm("mov.b64 {%0,%1},%2;" : "=f"(lo), "=f"(hi) : "l"(v));
}

// ---------------- kernel A: adaptive avg pool + row mean ----------------
__global__ void pool_kernel(const float* __restrict__ x) {
    int row = blockIdx.x;
    const float4* xr = (const float4*)(x + (size_t)row*TDIM);
    __shared__ float s_part[NF4];
    __shared__ float s_win[PDIM];
    int tid = threadIdx.x;                 // 256 threads
    for (int i = tid; i < NF4; i += 256) {
        float4 v = xr[i];
        s_part[i] = (v.x + v.y) + (v.z + v.w);
    }
    __syncthreads();
    if (tid < PDIM) {
        float s = 0.f;
        #pragma unroll
        for (int k = 0; k < 10; k++) s += s_part[tid*10 + k];
        s_win[tid] = s;
        g_pooled[row*PDIM + tid] = s * (1.0f/WIN);
    }
    __syncthreads();
    if (tid < 32) {
        float t = 0.f;
        for (int w = tid; w < PDIM; w += 32) t += s_win[w];
        #pragma unroll
        for (int off = 16; off; off >>= 1) t += __shfl_down_sync(0xffffffffu, t, off);
        if (tid == 0) g_xmean[row] = t * (1.0f/TDIM);
    }
}

// ---------------- kernel B: A = (Wk^T Wq)/16, wqb = (Wq^T bk)/16 ----------------
__global__ void prep_kernel(const float* __restrict__ Wk,
                            const float* __restrict__ Wq,
                            const float* __restrict__ bk) {
    int i = blockIdx.x;        // 0..99 -> A row i ; 100 -> wqb
    int j = threadIdx.x;       // 128 threads, use j<100
    if (j >= PDIM) return;
    float acc = 0.f;
    if (i < PDIM) {
        for (int d = 0; d < KD; d++)
            acc += Wk[d*PDIM + i] * Wq[d*PDIM + j];
        g_Amat[i*PDIM + j] = acc * (1.0f/16.0f);
    } else {
        for (int d = 0; d < KD; d++)
            acc += Wq[d*PDIM + j] * bk[d];
        g_wqb[j] = acc * (1.0f/16.0f);
    }
}

// ---------------- kernel B2: Dt = (P A)^T, Pt = P^T, v = P.wqb ----------------
// grid ROWS/64 = 128 blocks, 256 threads
__global__ void dv_kernel() {
    extern __shared__ float sm[];
    float* sA    = sm;                    // 10000
    float* sPT   = sA + PDIM*PDIM;        // 100*68
    float* s_wqb = sPT + PDIM*DVPAD;      // 100
    int row0 = blockIdx.x * 64;
    int b  = row0 >> 9;
    int f0 = row0 & (FDIM-1);
    int tid = threadIdx.x, tx = tid & 15, ty = tid >> 4;

    for (int idx = tid; idx < PDIM*PDIM; idx += 256) sA[idx] = g_Amat[idx];
    if (tid < PDIM) s_wqb[tid] = g_wqb[tid];
    for (int idx = tid; idx < 64*PDIM; idx += 256) {
        int r = idx / PDIM, i = idx % PDIM;
        sPT[i*DVPAD + r] = g_pooled[(row0 + r)*PDIM + i];
    }
    __syncthreads();

    // Dt[i2][f0+r] = sum_i P[r][i] A[i][i2]
    for (int i2 = ty; i2 < PDIM; i2 += 16) {
        float4 acc = make_float4(0.f,0.f,0.f,0.f);
        for (int i = 0; i < PDIM; i++) {
            float a = sA[i*PDIM + i2];
            float4 p = *(const float4*)(sPT + i*DVPAD + 4*tx);
            acc.x += a*p.x; acc.y += a*p.y; acc.z += a*p.z; acc.w += a*p.w;
        }
        *(float4*)(g_Dt + ((size_t)b*PDIM + i2)*FDIM + f0 + 4*tx) = acc;
    }
    // Pt copy
    for (int idx = tid; idx < PDIM*64; idx += 256) {
        int i = idx >> 6, r = idx & 63;
        g_Pt[((size_t)b*PDIM + i)*FDIM + f0 + r] = sPT[i*DVPAD + r];
    }
    // v
    if (tid < 64) {
        float v = 0.f;
        for (int i = 0; i < PDIM; i++) v += sPT[i*DVPAD + tid] * s_wqb[i];
        g_v[row0 + tid] = v;
    }
}

// ---------------- kernel C: scores = D P^T + v ; online softmax -> fw ----------------
// grid (FDIM/FT, BATCH), 256 threads (16x16), 4x4 micro-tile, f32x2 packed FMA
__global__ void att_kernel() {
    extern __shared__ float sm[];
    float* sDT  = sm;                 // 100*64
    float* sPT  = sDT + PDIM*FT;      // 100*64
    float* s_v  = sPT + PDIM*GT;      // 64
    float* s_xm = s_v + GT;           // 64

    int b  = blockIdx.y;
    int f0 = blockIdx.x * FT;
    int tid = threadIdx.x;
    int tx = tid & 15, ty = tid >> 4;

    const float* Dtb = g_Dt + (size_t)b*PDIM*FDIM;
    const float* Ptb = g_Pt + (size_t)b*PDIM*FDIM;

    for (int idx = tid; idx < PDIM*FT; idx += 256) {
        int i2 = idx >> 6, r = idx & 63;
        sDT[i2*FT + r] = Dtb[i2*FDIM + f0 + r];
    }

    float num[4] = {0.f,0.f,0.f,0.f};
    float den[4] = {0.f,0.f,0.f,0.f};

    for (int g0 = 0; g0 < FDIM; g0 += GT) {
        __syncthreads();   // prev tile consumed (also covers first sDT fill)
        for (int idx = tid; idx < PDIM*GT; idx += 256) {
            int i = idx >> 6, g = idx & 63;
            sPT[i*GT + g] = Ptb[i*FDIM + g0 + g];
        }
        if (tid < GT) {
            s_v [tid] = g_v    [b*FDIM + g0 + tid];
            s_xm[tid] = g_xmean[b*FDIM + g0 + tid];
        }
        __syncthreads();

        unsigned long long acc[4][2];
        #pragma unroll
        for (int rk = 0; rk < 4; rk++) { acc[rk][0] = 0ull; acc[rk][1] = 0ull; }

        #pragma unroll 2
        for (int i2 = 0; i2 < PDIM; i2++) {
            float4 d = *(const float4*)(sDT + i2*FT + 4*ty);
            float4 p = *(const float4*)(sPT + i2*GT + 4*tx);
            unsigned long long p01 = pk2(p.x, p.y);
            unsigned long long p23 = pk2(p.z, p.w);
            unsigned long long d0 = pk2(d.x, d.x);
            unsigned long long d1 = pk2(d.y, d.y);
            unsigned long long d2 = pk2(d.z, d.z);
            unsigned long long d3 = pk2(d.w, d.w);
            acc[0][0] = fma2(d0, p01, acc[0][0]);
            acc[0][1] = fma2(d0, p23, acc[0][1]);
            acc[1][0] = fma2(d1, p01, acc[1][0]);
            acc[1][1] = fma2(d1, p23, acc[1][1]);
            acc[2][0] = fma2(d2, p01, acc[2][0]);
            acc[2][1] = fma2(d2, p23, acc[2][1]);
            acc[3][0] = fma2(d3, p01, acc[3][0]);
            acc[3][1] = fma2(d3, p23, acc[3][1]);
        }

        float v0 = s_v[4*tx], v1 = s_v[4*tx+1], v2 = s_v[4*tx+2], v3 = s_v[4*tx+3];
        float m0 = s_xm[4*tx], m1 = s_xm[4*tx+1], m2 = s_xm[4*tx+2], m3 = s_xm[4*tx+3];
        #pragma unroll
        for (int rk = 0; rk < 4; rk++) {
            float s0, s1, s2, s3;
            unpk2(acc[rk][0], s0, s1);
            unpk2(acc[rk][1], s2, s3);
            float e0 = __expf(s0 + v0);   // scores ~1e-2 -> no max subtraction needed
            float e1 = __expf(s1 + v1);
            float e2 = __expf(s2 + v2);
            float e3 = __expf(s3 + v3);
            den[rk] += (e0 + e1) + (e2 + e3);
            num[rk] += (e0*m0 + e1*m1) + (e2*m2 + e3*m3);
        }
    }

    #pragma unroll
    for (int rk = 0; rk < 4; rk++) {
        float n = num[rk], d = den[rk];
        #pragma unroll
        for (int off = 8; off; off >>= 1) {
            n += __shfl_down_sync(0xffffffffu, n, off, 16);
            d += __shfl_down_sync(0xffffffffu, d, off, 16);
        }
        if (tx == 0) g_fw[b*FDIM + f0 + 4*ty + rk] = n / d;
    }
}

// ---------------- kernel D: per-batch min/max normalize fused with out = x*fw_n ----------------
__global__ void scale_kernel(const float* __restrict__ x, float* __restrict__ out) {
    int row = blockIdx.x;
    int b = row >> 9;
    int tid = threadIdx.x;     // 256
    const float* fwb = g_fw + (b << 9);
    float a0 = fwb[tid], a1 = fwb[tid + 256];
    float mn = fminf(a0, a1), mx = fmaxf(a0, a1);
    __shared__ float smn[8], smx[8], s_mi, s_ma;
    #pragma unroll
    for (int off = 16; off; off >>= 1) {
        mn = fminf(mn, __shfl_down_sync(0xffffffffu, mn, off));
        mx = fmaxf(mx, __shfl_down_sync(0xffffffffu, mx, off));
    }
    if ((tid & 31) == 0) { smn[tid >> 5] = mn; smx[tid >> 5] = mx; }
    __syncthreads();
    if (tid == 0) {
        float mi = smn[0], ma = smx[0];
        #pragma unroll
        for (int w = 1; w < 8; w++) { mi = fminf(mi, smn[w]); ma = fmaxf(ma, smx[w]); }
        s_mi = mi; s_ma = ma;
    }
    __syncthreads();
    float s = (fwb[row & 511] - s_mi) / (s_ma - s_mi) + 1e-6f;

    const float4* xr = (const float4*)(x + (size_t)row*TDIM);
    float4* orow = (float4*)(out + (size_t)row*TDIM);
    for (int i = tid; i < NF4; i += 256) {
        float4 v = xr[i];
        v.x *= s; v.y *= s; v.z *= s; v.w *= s;
        orow[i] = v;
    }
}

// ---------------- launch ----------------
extern "C" void kernel_launch(void* const* d_in, const int* in_sizes, int n_in,
                              void* d_out, int out_size) {
    const float* x  = (const float*)d_in[0];
    const float* Wk = (const float*)d_in[1];
    const float* bk = (const float*)d_in[2];
    const float* Wq = (const float*)d_in[3];
    const float* bq = (const float*)d_in[4];
    (void)bq; (void)in_sizes; (void)n_in; (void)out_size;
    float* out = (float*)d_out;

    const int smem_dv  = (PDIM*PDIM + PDIM*DVPAD + PDIM) * sizeof(float);       // ~67.6KB
    const int smem_att = (PDIM*FT + PDIM*GT + 2*GT) * sizeof(float);            // ~51.7KB
    static bool attr_set = false;
    if (!attr_set) {
        cudaFuncSetAttribute(dv_kernel,  cudaFuncAttributeMaxDynamicSharedMemorySize, smem_dv);
        cudaFuncSetAttribute(att_kernel, cudaFuncAttributeMaxDynamicSharedMemorySize, smem_att);
        attr_set = true;
    }

    pool_kernel<<<ROWS, 256>>>(x);
    prep_kernel<<<PDIM + 1, 128>>>(Wk, Wq, bk);
    dv_kernel<<<ROWS/64, 256, smem_dv>>>();
    dim3 agrid(FDIM/FT, BATCH);
    att_kernel<<<agrid, 256, smem_att>>>();
    scale_kernel<<<ROWS, 256>>>(x, out);
}

// round 3
// speedup vs baseline: 1.1044x; 1.0957x over previous
#include <cuda_runtime.h>

#define BATCH 16
#define FDIM  512
#define TDIM  4000
#define PDIM  100
#define WIN   40
#define KD    256
#define ROWS  (BATCH*FDIM)     // 8192
#define NF4   (TDIM/4)         // 1000 float4 per row

#define FT 64                  // f-tile rows per att block
#define GT 64                  // g-tile cols per iteration
#define GSPLIT 4               // g-range splits (parallelism)
#define GCHUNK (FDIM/GSPLIT)   // 128 g per block
#define DVPAD 68               // padded stride in dv transpose tile (16B-aligned)

// ---------------- scratch (__device__ globals; no allocation) ----------------
__device__ float g_pooled[ROWS*PDIM];        // P [B*F,100]
__device__ float g_xmean [ROWS];
__device__ float g_Amat  [PDIM*PDIM];        // (Wk^T Wq)/16
__device__ float g_wqb   [PDIM];             // (Wq^T bk)/16
__device__ float g_Dt    [BATCH*PDIM*FDIM];  // D^T per batch: [b][i2][f]
__device__ float g_Pt    [BATCH*PDIM*FDIM];  // P^T per batch: [b][i][g]
__device__ float g_v     [ROWS];             // v = P . wqb
__device__ float g_numP  [GSPLIT*ROWS];      // partial softmax numerators
__device__ float g_denP  [GSPLIT*ROWS];      // partial softmax denominators
__device__ float g_fw    [ROWS];

// ---------------- packed f32x2 helpers ----------------
__device__ __forceinline__ unsigned long long pk2(float lo, float hi) {
    unsigned long long r;
    asm("mov.b64 %0,{%1,%2};" : "=l"(r) : "f"(lo), "f"(hi));
    return r;
}
__device__ __forceinline__ unsigned long long fma2(unsigned long long a,
                                                   unsigned long long b,
                                                   unsigned long long c) {
    unsigned long long d;
    asm("fma.rn.f32x2 %0,%1,%2,%3;" : "=l"(d) : "l"(a), "l"(b), "l"(c));
    return d;
}
__device__ __forceinline__ void unpk2(unsigned long long v, float& lo, float& hi) {
    asm("mov.b64 {%0,%1},%2;" : "=f"(lo), "=f"(hi) : "l"(v));
}

// ---------------- kernel A: adaptive avg pool + row mean ----------------
__global__ void pool_kernel(const float* __restrict__ x) {
    int row = blockIdx.x;
    const float4* xr = (const float4*)(x + (size_t)row*TDIM);
    __shared__ float s_part[NF4];
    __shared__ float s_win[PDIM];
    int tid = threadIdx.x;                 // 256 threads
    for (int i = tid; i < NF4; i += 256) {
        float4 v = xr[i];
        s_part[i] = (v.x + v.y) + (v.z + v.w);
    }
    __syncthreads();
    if (tid < PDIM) {
        float s = 0.f;
        #pragma unroll
        for (int k = 0; k < 10; k++) s += s_part[tid*10 + k];
        s_win[tid] = s;
        g_pooled[row*PDIM + tid] = s * (1.0f/WIN);
    }
    __syncthreads();
    if (tid < 32) {
        float t = 0.f;
        for (int w = tid; w < PDIM; w += 32) t += s_win[w];
        #pragma unroll
        for (int off = 16; off; off >>= 1) t += __shfl_down_sync(0xffffffffu, t, off);
        if (tid == 0) g_xmean[row] = t * (1.0f/TDIM);
    }
}

// ---------------- kernel B: A = (Wk^T Wq)/16, wqb = (Wq^T bk)/16 ----------------
__global__ void prep_kernel(const float* __restrict__ Wk,
                            const float* __restrict__ Wq,
                            const float* __restrict__ bk) {
    int i = blockIdx.x;        // 0..99 -> A row i ; 100 -> wqb
    int j = threadIdx.x;       // 128 threads, use j<100
    if (j >= PDIM) return;
    float acc = 0.f;
    if (i < PDIM) {
        for (int d = 0; d < KD; d++)
            acc += Wk[d*PDIM + i] * Wq[d*PDIM + j];
        g_Amat[i*PDIM + j] = acc * (1.0f/16.0f);
    } else {
        for (int d = 0; d < KD; d++)
            acc += Wq[d*PDIM + j] * bk[d];
        g_wqb[j] = acc * (1.0f/16.0f);
    }
}

// ---------------- kernel B2: Dt = (P A)^T, Pt = P^T, v = P.wqb ----------------
__global__ void dv_kernel() {
    extern __shared__ float sm[];
    float* sA    = sm;                    // 10000
    float* sPT   = sA + PDIM*PDIM;        // 100*68
    float* s_wqb = sPT + PDIM*DVPAD;      // 100
    int row0 = blockIdx.x * 64;
    int b  = row0 >> 9;
    int f0 = row0 & (FDIM-1);
    int tid = threadIdx.x, tx = tid & 15, ty = tid >> 4;

    for (int idx = tid; idx < PDIM*PDIM; idx += 256) sA[idx] = g_Amat[idx];
    if (tid < PDIM) s_wqb[tid] = g_wqb[tid];
    for (int idx = tid; idx < 64*PDIM; idx += 256) {
        int r = idx / PDIM, i = idx % PDIM;
        sPT[i*DVPAD + r] = g_pooled[(row0 + r)*PDIM + i];
    }
    __syncthreads();

    for (int i2 = ty; i2 < PDIM; i2 += 16) {
        float4 acc = make_float4(0.f,0.f,0.f,0.f);
        for (int i = 0; i < PDIM; i++) {
            float a = sA[i*PDIM + i2];
            float4 p = *(const float4*)(sPT + i*DVPAD + 4*tx);
            acc.x += a*p.x; acc.y += a*p.y; acc.z += a*p.z; acc.w += a*p.w;
        }
        *(float4*)(g_Dt + ((size_t)b*PDIM + i2)*FDIM + f0 + 4*tx) = acc;
    }
    for (int idx = tid; idx < PDIM*64; idx += 256) {
        int i = idx >> 6, r = idx & 63;
        g_Pt[((size_t)b*PDIM + i)*FDIM + f0 + r] = sPT[i*DVPAD + r];
    }
    if (tid < 64) {
        float v = 0.f;
        for (int i = 0; i < PDIM; i++) v += sPT[i*DVPAD + tid] * s_wqb[i];
        g_v[row0 + tid] = v;
    }
}

// ---------------- kernel C: partial scores + online softmax over a g-slice ----------------
// grid (FDIM/FT, BATCH, GSPLIT), 256 threads (16x16), 4x4 micro-tile, f32x2 FMA
__global__ void att_kernel() {
    extern __shared__ float sm[];
    float* sDT  = sm;                 // 100*64
    float* sPT  = sDT + PDIM*FT;      // 100*64
    float* s_v  = sPT + PDIM*GT;      // 64
    float* s_xm = s_v + GT;           // 64

    int b  = blockIdx.y;
    int f0 = blockIdx.x * FT;
    int gs = blockIdx.z;
    int tid = threadIdx.x;
    int tx = tid & 15, ty = tid >> 4;

    const float* Dtb = g_Dt + (size_t)b*PDIM*FDIM;
    const float* Ptb = g_Pt + (size_t)b*PDIM*FDIM;

    for (int idx = tid; idx < PDIM*FT; idx += 256) {
        int i2 = idx >> 6, r = idx & 63;
        sDT[i2*FT + r] = Dtb[i2*FDIM + f0 + r];
    }

    float num[4] = {0.f,0.f,0.f,0.f};
    float den[4] = {0.f,0.f,0.f,0.f};

    for (int g0 = gs*GCHUNK; g0 < (gs+1)*GCHUNK; g0 += GT) {
        __syncthreads();   // prev tile consumed (also covers first sDT fill)
        for (int idx = tid; idx < PDIM*GT; idx += 256) {
            int i = idx >> 6, g = idx & 63;
            sPT[i*GT + g] = Ptb[i*FDIM + g0 + g];
        }
        if (tid < GT) {
            s_v [tid] = g_v    [b*FDIM + g0 + tid];
            s_xm[tid] = g_xmean[b*FDIM + g0 + tid];
        }
        __syncthreads();

        unsigned long long acc[4][2];
        #pragma unroll
        for (int rk = 0; rk < 4; rk++) { acc[rk][0] = 0ull; acc[rk][1] = 0ull; }

        #pragma unroll 4
        for (int i2 = 0; i2 < PDIM; i2++) {
            float4 d = *(const float4*)(sDT + i2*FT + 4*ty);
            float4 p = *(const float4*)(sPT + i2*GT + 4*tx);
            unsigned long long p01 = pk2(p.x, p.y);
            unsigned long long p23 = pk2(p.z, p.w);
            unsigned long long d0 = pk2(d.x, d.x);
            unsigned long long d1 = pk2(d.y, d.y);
            unsigned long long d2 = pk2(d.z, d.z);
            unsigned long long d3 = pk2(d.w, d.w);
            acc[0][0] = fma2(d0, p01, acc[0][0]);
            acc[0][1] = fma2(d0, p23, acc[0][1]);
            acc[1][0] = fma2(d1, p01, acc[1][0]);
            acc[1][1] = fma2(d1, p23, acc[1][1]);
            acc[2][0] = fma2(d2, p01, acc[2][0]);
            acc[2][1] = fma2(d2, p23, acc[2][1]);
            acc[3][0] = fma2(d3, p01, acc[3][0]);
            acc[3][1] = fma2(d3, p23, acc[3][1]);
        }

        float v0 = s_v[4*tx], v1 = s_v[4*tx+1], v2 = s_v[4*tx+2], v3 = s_v[4*tx+3];
        float m0 = s_xm[4*tx], m1 = s_xm[4*tx+1], m2 = s_xm[4*tx+2], m3 = s_xm[4*tx+3];
        #pragma unroll
        for (int rk = 0; rk < 4; rk++) {
            float s0, s1, s2, s3;
            unpk2(acc[rk][0], s0, s1);
            unpk2(acc[rk][1], s2, s3);
            float e0 = __expf(s0 + v0);   // scores ~1e-2 -> no max subtraction needed
            float e1 = __expf(s1 + v1);
            float e2 = __expf(s2 + v2);
            float e3 = __expf(s3 + v3);
            den[rk] += (e0 + e1) + (e2 + e3);
            num[rk] += (e0*m0 + e1*m1) + (e2*m2 + e3*m3);
        }
    }

    #pragma unroll
    for (int rk = 0; rk < 4; rk++) {
        float n = num[rk], d = den[rk];
        #pragma unroll
        for (int off = 8; off; off >>= 1) {
            n += __shfl_down_sync(0xffffffffu, n, off, 16);
            d += __shfl_down_sync(0xffffffffu, d, off, 16);
        }
        if (tx == 0) {
            int r = b*FDIM + f0 + 4*ty + rk;
            g_numP[gs*ROWS + r] = n;
            g_denP[gs*ROWS + r] = d;
        }
    }
}

// ---------------- kernel C2: combine partials -> fw ----------------
__global__ void fw_kernel() {
    int r = blockIdx.x*256 + threadIdx.x;
    float n = 0.f, d = 0.f;
    #pragma unroll
    for (int s = 0; s < GSPLIT; s++) {
        n += g_numP[s*ROWS + r];
        d += g_denP[s*ROWS + r];
    }
    g_fw[r] = n / d;
}

// ---------------- kernel D: per-batch min/max normalize fused with out = x*fw_n ----------------
__global__ void scale_kernel(const float* __restrict__ x, float* __restrict__ out) {
    int row = blockIdx.x;
    int b = row >> 9;
    int tid = threadIdx.x;     // 256
    const float* fwb = g_fw + (b << 9);
    float a0 = fwb[tid], a1 = fwb[tid + 256];
    float mn = fminf(a0, a1), mx = fmaxf(a0, a1);
    __shared__ float smn[8], smx[8], s_mi, s_ma;
    #pragma unroll
    for (int off = 16; off; off >>= 1) {
        mn = fminf(mn, __shfl_down_sync(0xffffffffu, mn, off));
        mx = fmaxf(mx, __shfl_down_sync(0xffffffffu, mx, off));
    }
    if ((tid & 31) == 0) { smn[tid >> 5] = mn; smx[tid >> 5] = mx; }
    __syncthreads();
    if (tid == 0) {
        float mi = smn[0], ma = smx[0];
        #pragma unroll
        for (int w = 1; w < 8; w++) { mi = fminf(mi, smn[w]); ma = fmaxf(ma, smx[w]); }
        s_mi = mi; s_ma = ma;
    }
    __syncthreads();
    float s = (fwb[row & 511] - s_mi) / (s_ma - s_mi) + 1e-6f;

    const float4* xr = (const float4*)(x + (size_t)row*TDIM);
    float4* orow = (float4*)(out + (size_t)row*TDIM);
    for (int i = tid; i < NF4; i += 256) {
        float4 v = xr[i];
        v.x *= s; v.y *= s; v.z *= s; v.w *= s;
        orow[i] = v;
    }
}

// ---------------- launch ----------------
extern "C" void kernel_launch(void* const* d_in, const int* in_sizes, int n_in,
                              void* d_out, int out_size) {
    const float* x  = (const float*)d_in[0];
    const float* Wk = (const float*)d_in[1];
    const float* bk = (const float*)d_in[2];
    const float* Wq = (const float*)d_in[3];
    const float* bq = (const float*)d_in[4];
    (void)bq; (void)in_sizes; (void)n_in; (void)out_size;
    float* out = (float*)d_out;

    const int smem_dv  = (PDIM*PDIM + PDIM*DVPAD + PDIM) * sizeof(float);       // ~67.6KB
    const int smem_att = (PDIM*FT + PDIM*GT + 2*GT) * sizeof(float);            // ~51.7KB
    static bool attr_set = false;
    if (!attr_set) {
        cudaFuncSetAttribute(dv_kernel,  cudaFuncAttributeMaxDynamicSharedMemorySize, smem_dv);
        cudaFuncSetAttribute(att_kernel, cudaFuncAttributeMaxDynamicSharedMemorySize, smem_att);
        attr_set = true;
    }

    pool_kernel<<<ROWS, 256>>>(x);
    prep_kernel<<<PDIM + 1, 128>>>(Wk, Wq, bk);
    dv_kernel<<<ROWS/64, 256, smem_dv>>>();
    dim3 agrid(FDIM/FT, BATCH, GSPLIT);
    att_kernel<<<agrid, 256, smem_att>>>();
    fw_kernel<<<ROWS/256, 256>>>();
    scale_kernel<<<ROWS, 256>>>(x, out);
}

// round 4
// speedup vs baseline: 1.1088x; 1.0040x over previous
#include <cuda_runtime.h>

#define BATCH 16
#define FDIM  512
#define TDIM  4000
#define PDIM  100
#define WIN   40
#define KD    256
#define ROWS  (BATCH*FDIM)     // 8192
#define NF4   (TDIM/4)         // 1000 float4 per row

#define FT 64                  // f-tile rows per att block
#define GT 64                  // g-tile cols per att block
#define GSPLIT 8               // one g-tile per block
#define DVPAD 68               // padded stride in dv transpose tile
#define DVSPLIT 4              // i2-range splits in dv
#define DVI2 (PDIM/DVSPLIT)    // 25 i2 per dv block

// ---------------- scratch (__device__ globals; no allocation) ----------------
__device__ float g_pooled[ROWS*PDIM];        // P [B*F,100]
__device__ float g_xmean [ROWS];
__device__ float g_Amat  [PDIM*PDIM];        // (Wk^T Wq)/16
__device__ float g_wqb   [PDIM];             // (Wq^T bk)/16
__device__ float g_Dt    [BATCH*PDIM*FDIM];  // D^T per batch: [b][i2][f]
__device__ float g_Pt    [BATCH*PDIM*FDIM];  // P^T per batch: [b][i][g]
__device__ float g_v     [ROWS];             // v = P . wqb
__device__ float g_numP  [GSPLIT*ROWS];      // partial softmax numerators
__device__ float g_denP  [GSPLIT*ROWS];      // partial softmax denominators
__device__ float g_fw    [ROWS];

// ---------------- packed f32x2 helpers ----------------
__device__ __forceinline__ unsigned long long pk2(float lo, float hi) {
    unsigned long long r;
    asm("mov.b64 %0,{%1,%2};" : "=l"(r) : "f"(lo), "f"(hi));
    return r;
}
__device__ __forceinline__ unsigned long long fma2(unsigned long long a,
                                                   unsigned long long b,
                                                   unsigned long long c) {
    unsigned long long d;
    asm("fma.rn.f32x2 %0,%1,%2,%3;" : "=l"(d) : "l"(a), "l"(b), "l"(c));
    return d;
}
__device__ __forceinline__ void unpk2(unsigned long long v, float& lo, float& hi) {
    asm("mov.b64 {%0,%1},%2;" : "=f"(lo), "=f"(hi) : "l"(v));
}

// ---------------- kernel A: adaptive avg pool + row mean ----------------
__global__ void pool_kernel(const float* __restrict__ x) {
    int row = blockIdx.x;
    const float4* xr = (const float4*)(x + (size_t)row*TDIM);
    __shared__ float s_part[NF4];
    __shared__ float s_win[PDIM];
    int tid = threadIdx.x;                 // 256 threads
    for (int i = tid; i < NF4; i += 256) {
        float4 v = xr[i];
        s_part[i] = (v.x + v.y) + (v.z + v.w);
    }
    __syncthreads();
    if (tid < PDIM) {
        float s = 0.f;
        #pragma unroll
        for (int k = 0; k < 10; k++) s += s_part[tid*10 + k];
        s_win[tid] = s;
        g_pooled[row*PDIM + tid] = s * (1.0f/WIN);
    }
    __syncthreads();
    if (tid < 32) {
        float t = 0.f;
        for (int w = tid; w < PDIM; w += 32) t += s_win[w];
        #pragma unroll
        for (int off = 16; off; off >>= 1) t += __shfl_down_sync(0xffffffffu, t, off);
        if (tid == 0) g_xmean[row] = t * (1.0f/TDIM);
    }
}

// ---------------- kernel B: A = (Wk^T Wq)/16, wqb = (Wq^T bk)/16 ----------------
__global__ void prep_kernel(const float* __restrict__ Wk,
                            const float* __restrict__ Wq,
                            const float* __restrict__ bk) {
    int i = blockIdx.x;        // 0..99 -> A row i ; 100 -> wqb
    int j = threadIdx.x;       // 128 threads, use j<100
    if (j >= PDIM) return;
    float acc = 0.f;
    if (i < PDIM) {
        #pragma unroll 8
        for (int d = 0; d < KD; d++)
            acc += Wk[d*PDIM + i] * Wq[d*PDIM + j];
        g_Amat[i*PDIM + j] = acc * (1.0f/16.0f);
    } else {
        #pragma unroll 8
        for (int d = 0; d < KD; d++)
            acc += Wq[d*PDIM + j] * bk[d];
        g_wqb[j] = acc * (1.0f/16.0f);
    }
}

// ---------------- kernel B2: Dt = (P A)^T (i2-split), Pt = P^T, v = P.wqb ----------------
// grid (ROWS/64, DVSPLIT), 256 threads
__global__ void dv_kernel() {
    extern __shared__ float sm[];
    float* sAq   = sm;                    // 100*25 slice of A columns
    float* sPT   = sAq + PDIM*DVI2;       // 100*68
    float* s_wqb = sPT + PDIM*DVPAD;      // 100
    int row0 = blockIdx.x * 64;
    int q    = blockIdx.y;                // i2 quarter
    int b  = row0 >> 9;
    int f0 = row0 & (FDIM-1);
    int tid = threadIdx.x, tx = tid & 15, ty = tid >> 4;
    int i2base = q * DVI2;

    // A column slice: sAq[i][j2] = A[i][i2base+j2]
    for (int idx = tid; idx < PDIM*DVI2; idx += 256) {
        int i = idx / DVI2, j2 = idx % DVI2;
        sAq[idx] = g_Amat[i*PDIM + i2base + j2];
    }
    if (q == 0 && tid < PDIM) s_wqb[tid] = g_wqb[tid];
    for (int idx = tid; idx < 64*PDIM; idx += 256) {
        int r = idx / PDIM, i = idx % PDIM;
        sPT[i*DVPAD + r] = g_pooled[(row0 + r)*PDIM + i];
    }
    __syncthreads();

    // Dt[i2][f0+r] = sum_i P[r][i] A[i][i2], i2 in this quarter
    for (int j2 = ty; j2 < DVI2; j2 += 16) {
        float4 acc = make_float4(0.f,0.f,0.f,0.f);
        #pragma unroll 4
        for (int i = 0; i < PDIM; i++) {
            float a = sAq[i*DVI2 + j2];
            float4 p = *(const float4*)(sPT + i*DVPAD + 4*tx);
            acc.x += a*p.x; acc.y += a*p.y; acc.z += a*p.z; acc.w += a*p.w;
        }
        *(float4*)(g_Dt + ((size_t)b*PDIM + i2base + j2)*FDIM + f0 + 4*tx) = acc;
    }
    if (q == 1) {
        for (int idx = tid; idx < PDIM*64; idx += 256) {
            int i = idx >> 6, r = idx & 63;
            g_Pt[((size_t)b*PDIM + i)*FDIM + f0 + r] = sPT[i*DVPAD + r];
        }
    }
    if (q == 0 && tid < 64) {
        float v = 0.f;
        #pragma unroll 4
        for (int i = 0; i < PDIM; i++) v += sPT[i*DVPAD + tid] * s_wqb[i];
        g_v[row0 + tid] = v;
    }
}

// ---------------- kernel C: partial scores + online softmax, one g-tile per block ----------------
// grid (FDIM/FT, BATCH, GSPLIT), 256 threads (16x16), 4x4 micro-tile, f32x2 FMA
__global__ void att_kernel() {
    extern __shared__ float sm[];
    float* sDT  = sm;                 // 100*64
    float* sPT  = sDT + PDIM*FT;      // 100*64
    float* s_v  = sPT + PDIM*GT;      // 64
    float* s_xm = s_v + GT;           // 64

    int b  = blockIdx.y;
    int f0 = blockIdx.x * FT;
    int g0 = blockIdx.z * GT;
    int tid = threadIdx.x;
    int tx = tid & 15, ty = tid >> 4;

    const float* Dtb = g_Dt + (size_t)b*PDIM*FDIM;
    const float* Ptb = g_Pt + (size_t)b*PDIM*FDIM;

    for (int idx = tid; idx < PDIM*FT; idx += 256) {
        int i2 = idx >> 6, r = idx & 63;
        sDT[i2*FT + r] = Dtb[i2*FDIM + f0 + r];
    }
    for (int idx = tid; idx < PDIM*GT; idx += 256) {
        int i = idx >> 6, g = idx & 63;
        sPT[i*GT + g] = Ptb[i*FDIM + g0 + g];
    }
    if (tid < GT) {
        s_v [tid] = g_v    [b*FDIM + g0 + tid];
        s_xm[tid] = g_xmean[b*FDIM + g0 + tid];
    }
    __syncthreads();

    unsigned long long acc[4][2];
    #pragma unroll
    for (int rk = 0; rk < 4; rk++) { acc[rk][0] = 0ull; acc[rk][1] = 0ull; }

    const ulonglong2* pbase = (const ulonglong2*)(sPT + 4*tx);
    const float4*     dbase = (const float4*)(sDT + 4*ty);

    #pragma unroll 4
    for (int i2 = 0; i2 < PDIM; i2++) {
        float4     d  = dbase[i2*(FT/4)];
        ulonglong2 pp = pbase[i2*(GT/4)];       // p01 = low pair, p23 = high pair (free packing)
        unsigned long long d0 = pk2(d.x, d.x);
        unsigned long long d1 = pk2(d.y, d.y);
        unsigned long long d2 = pk2(d.z, d.z);
        unsigned long long d3 = pk2(d.w, d.w);
        acc[0][0] = fma2(d0, pp.x, acc[0][0]);
        acc[0][1] = fma2(d0, pp.y, acc[0][1]);
        acc[1][0] = fma2(d1, pp.x, acc[1][0]);
        acc[1][1] = fma2(d1, pp.y, acc[1][1]);
        acc[2][0] = fma2(d2, pp.x, acc[2][0]);
        acc[2][1] = fma2(d2, pp.y, acc[2][1]);
        acc[3][0] = fma2(d3, pp.x, acc[3][0]);
        acc[3][1] = fma2(d3, pp.y, acc[3][1]);
    }

    float v0 = s_v[4*tx], v1 = s_v[4*tx+1], v2 = s_v[4*tx+2], v3 = s_v[4*tx+3];
    float m0 = s_xm[4*tx], m1 = s_xm[4*tx+1], m2 = s_xm[4*tx+2], m3 = s_xm[4*tx+3];
    float num[4], den[4];
    #pragma unroll
    for (int rk = 0; rk < 4; rk++) {
        float s0, s1, s2, s3;
        unpk2(acc[rk][0], s0, s1);
        unpk2(acc[rk][1], s2, s3);
        float e0 = __expf(s0 + v0);   // scores ~1e-2 -> no max subtraction needed
        float e1 = __expf(s1 + v1);
        float e2 = __expf(s2 + v2);
        float e3 = __expf(s3 + v3);
        den[rk] = (e0 + e1) + (e2 + e3);
        num[rk] = (e0*m0 + e1*m1) + (e2*m2 + e3*m3);
    }

    #pragma unroll
    for (int rk = 0; rk < 4; rk++) {
        float n = num[rk], d = den[rk];
        #pragma unroll
        for (int off = 8; off; off >>= 1) {
            n += __shfl_down_sync(0xffffffffu, n, off, 16);
            d += __shfl_down_sync(0xffffffffu, d, off, 16);
        }
        if (tx == 0) {
            int r = b*FDIM + f0 + 4*ty + rk;
            g_numP[blockIdx.z*ROWS + r] = n;
            g_denP[blockIdx.z*ROWS + r] = d;
        }
    }
}

// ---------------- kernel C2: combine partials -> fw ----------------
__global__ void fw_kernel() {
    int r = blockIdx.x*256 + threadIdx.x;
    float n = 0.f, d = 0.f;
    #pragma unroll
    for (int s = 0; s < GSPLIT; s++) {
        n += g_numP[s*ROWS + r];
        d += g_denP[s*ROWS + r];
    }
    g_fw[r] = n / d;
}

// ---------------- kernel D: per-batch min/max normalize fused with out = x*fw_n ----------------
__global__ void scale_kernel(const float* __restrict__ x, float* __restrict__ out) {
    int row = blockIdx.x;
    int b = row >> 9;
    int tid = threadIdx.x;     // 256
    const float* fwb = g_fw + (b << 9);
    float a0 = fwb[tid], a1 = fwb[tid + 256];
    float mn = fminf(a0, a1), mx = fmaxf(a0, a1);
    __shared__ float smn[8], smx[8], s_mi, s_ma;
    #pragma unroll
    for (int off = 16; off; off >>= 1) {
        mn = fminf(mn, __shfl_down_sync(0xffffffffu, mn, off));
        mx = fmaxf(mx, __shfl_down_sync(0xffffffffu, mx, off));
    }
    if ((tid & 31) == 0) { smn[tid >> 5] = mn; smx[tid >> 5] = mx; }
    __syncthreads();
    if (tid == 0) {
        float mi = smn[0], ma = smx[0];
        #pragma unroll
        for (int w = 1; w < 8; w++) { mi = fminf(mi, smn[w]); ma = fmaxf(ma, smx[w]); }
        s_mi = mi; s_ma = ma;
    }
    __syncthreads();
    float s = (fwb[row & 511] - s_mi) / (s_ma - s_mi) + 1e-6f;

    const float4* xr = (const float4*)(x + (size_t)row*TDIM);
    float4* orow = (float4*)(out + (size_t)row*TDIM);
    for (int i = tid; i < NF4; i += 256) {
        float4 v = xr[i];
        v.x *= s; v.y *= s; v.z *= s; v.w *= s;
        orow[i] = v;
    }
}

// ---------------- launch ----------------
extern "C" void kernel_launch(void* const* d_in, const int* in_sizes, int n_in,
                              void* d_out, int out_size) {
    const float* x  = (const float*)d_in[0];
    const float* Wk = (const float*)d_in[1];
    const float* bk = (const float*)d_in[2];
    const float* Wq = (const float*)d_in[3];
    const float* bq = (const float*)d_in[4];
    (void)bq; (void)in_sizes; (void)n_in; (void)out_size;
    float* out = (float*)d_out;

    const int smem_dv  = (PDIM*DVI2 + PDIM*DVPAD + PDIM) * sizeof(float);       // ~37.6KB
    const int smem_att = (PDIM*FT + PDIM*GT + 2*GT) * sizeof(float);            // ~51.7KB
    static bool attr_set = false;
    if (!attr_set) {
        cudaFuncSetAttribute(dv_kernel,  cudaFuncAttributeMaxDynamicSharedMemorySize, smem_dv);
        cudaFuncSetAttribute(att_kernel, cudaFuncAttributeMaxDynamicSharedMemorySize, smem_att);
        attr_set = true;
    }

    pool_kernel<<<ROWS, 256>>>(x);
    prep_kernel<<<PDIM + 1, 128>>>(Wk, Wq, bk);
    dim3 dvgrid(ROWS/64, DVSPLIT);
    dv_kernel<<<dvgrid, 256, smem_dv>>>();
    dim3 agrid(FDIM/FT, BATCH, GSPLIT);
    att_kernel<<<agrid, 256, smem_att>>>();
    fw_kernel<<<ROWS/256, 256>>>();
    scale_kernel<<<ROWS, 256>>>(x, out);
}